// round 6
// baseline (speedup 1.0000x reference)
#include <cuda_runtime.h>
#include <cuda_fp16.h>
#include <math.h>

#define B_DIM 32
#define S_DIM 325
#define L_DIM 192
#define NSEQ (B_DIM * S_DIM)   // 10400
#define DH 128
#define NH 8
#define NEG_F (-1000000000.0f)

// ---- qk fp8 MMA kernel geometry ----
#define MSEQ 64                          // sequences per block (2 teams x 32)
#define WB 144                           // byte stride for W / h rows (128 + 16 pad)
#define NBLK ((NSEQ + MSEQ - 1) / MSEQ)  // 163
#define SM_W  (512 * WB)                 // 73728
#define SM_HA SM_W                       // h buffer 0: [64][WB] fp8
#define SM_HB (SM_W + 64 * WB)           // h buffer 1
#define SM_XS (SM_W + 2 * 64 * WB)       // x ring: [2 team][2 buf][32] f32 = 512B
#define QK_SMEM (SM_XS + 512)            // 92672 bytes

#define ATTN_SMEM ((32*129 + 32*336 + 32*193) * 4) // 84224 bytes

// ---- scratch (static device arrays; no allocation allowed) ----
__device__ float g_xT[L_DIM * NSEQ];            // x transposed [t][n]
__device__ float g_q[NH * NSEQ * DH];           // [h][n][d]
__device__ float g_k[NH * NSEQ * DH];           // [h][n][d]
__device__ float g_v[NH * NSEQ * L_DIM];        // [h][n][l]

__device__ __forceinline__ float sigf(float x) { return 1.0f / (1.0f + __expf(-x)); }
__device__ __forceinline__ float tanh_fast(float x) { return 2.0f / (1.0f + __expf(-2.0f * x)) - 1.0f; }

__device__ __forceinline__ __half2 tanh2(__half2 x) {
    unsigned y, xi = *(unsigned*)&x;
    asm("tanh.approx.f16x2 %0, %1;" : "=r"(y) : "r"(xi));
    return *(__half2*)&y;
}
__device__ __forceinline__ unsigned short f32x2_to_e4m3x2(float lo, float hi) {
    unsigned short r;
    asm("cvt.rn.satfinite.e4m3x2.f32 %0, %1, %2;" : "=h"(r) : "f"(hi), "f"(lo));
    return r;
}
__device__ __forceinline__ unsigned short h2_to_e4m3x2(__half2 v) {
    unsigned short r;
    unsigned vi = *(unsigned*)&v;
    asm("cvt.rn.satfinite.e4m3x2.f16x2 %0, %1;" : "=h"(r) : "r"(vi));
    return r;
}

__device__ __forceinline__ void ldsm4(unsigned& r0, unsigned& r1, unsigned& r2, unsigned& r3,
                                      const void* p) {
    unsigned a = (unsigned)__cvta_generic_to_shared(p);
    asm volatile("ldmatrix.sync.aligned.m8n8.x4.shared.b16 {%0,%1,%2,%3}, [%4];"
                 : "=r"(r0), "=r"(r1), "=r"(r2), "=r"(r3) : "r"(a));
}
__device__ __forceinline__ void mma_fp8(float* d, const unsigned* a, unsigned b0, unsigned b1) {
    asm volatile("mma.sync.aligned.m16n8k32.row.col.f32.e4m3.e4m3.f32 "
                 "{%0,%1,%2,%3}, {%4,%5,%6,%7}, {%8,%9}, {%0,%1,%2,%3};"
                 : "+f"(d[0]), "+f"(d[1]), "+f"(d[2]), "+f"(d[3])
                 : "r"(a[0]), "r"(a[1]), "r"(a[2]), "r"(a[3]), "r"(b0), "r"(b1));
}
__device__ __forceinline__ void team_bar(int T) {
    asm volatile("bar.sync %0, 256;" :: "r"(1 + T) : "memory");
}

// ---------------- x transpose: [n][t] -> [t][n] ----------------
__global__ void xT_kernel(const float* __restrict__ x) {
    int i = blockIdx.x * 256 + threadIdx.x;
    if (i < NSEQ * L_DIM) {
        int n = i / L_DIM, t = i - n * L_DIM;
        g_xT[t * NSEQ + n] = x[i];
    }
}

// ---------------- v LSTM (hidden size 1) ----------------
__global__ void v_lstm_kernel(const float* __restrict__ Wih, const float* __restrict__ Whh,
                              const float* __restrict__ bih, const float* __restrict__ bhh) {
    int n = blockIdx.x * 256 + threadIdx.x;
    int h = blockIdx.y;
    if (n >= NSEQ) return;
    float wi[4], wh[4], bb[4];
#pragma unroll
    for (int g = 0; g < 4; g++) {
        wi[g] = Wih[h * 4 + g];
        wh[g] = Whh[h * 4 + g];
        bb[g] = bih[h * 4 + g] + bhh[h * 4 + g];
    }
    float hv = 0.f, c = 0.f;
    float4 buf;
    float* vout = g_v + ((size_t)h * NSEQ + n) * L_DIM;
    for (int t = 0; t < L_DIM; t++) {
        float xv = g_xT[t * NSEQ + n];
        float zi = xv * wi[0] + hv * wh[0] + bb[0];
        float zf = xv * wi[1] + hv * wh[1] + bb[1];
        float zg = xv * wi[2] + hv * wh[2] + bb[2];
        float zo = xv * wi[3] + hv * wh[3] + bb[3];
        c = sigf(zf) * c + sigf(zi) * tanh_fast(zg);
        hv = sigf(zo) * tanh_fast(c);
        ((float*)&buf)[t & 3] = hv;
        if ((t & 3) == 3) *(float4*)(vout + (t - 3)) = buf;
    }
}

// ---------------- q/k LSTM on fp8 tensor cores (m16n8k32 e4m3) ----------------
// grid (163, 16). 512 threads = 16 warps = 2 teams x 8 warps. Team T handles
// sequences [32T, 32T+32). Warp (T,wv) computes z for its team's 32 seqs x 64
// permuted gate columns (units [16wv,16wv+16) x 4 gates) and writes the fp8 h
// chunk = K-columns [16wv,16wv+16). Sync: ONE named barrier per team per step
// (deadlock-free; cross-team phase stagger provides pipe overlap on SMSPs).
__global__ __launch_bounds__(512, 1) void qk_lstm_fp8(
    const float* __restrict__ qWih, const float* __restrict__ qWhh,
    const float* __restrict__ qbih, const float* __restrict__ qbhh,
    const float* __restrict__ kWih, const float* __restrict__ kWhh,
    const float* __restrict__ kbih, const float* __restrict__ kbhh) {
    extern __shared__ char sm[];
    unsigned char* ws = (unsigned char*)sm;          // permuted Whh e4m3 [512][WB]
    unsigned char* hbuf[2] = {(unsigned char*)(sm + SM_HA), (unsigned char*)(sm + SM_HB)};
    float* xs = (float*)(sm + SM_XS);                // [team][buf][32]

    const int tid = threadIdx.x;
    const int warp = tid >> 5, lane = tid & 31;
    const int T = warp >> 3, wv = warp & 7;
    const int q4 = lane >> 2, r4 = lane & 3;
    const int grp = lane >> 3, ro = lane & 7;
    const int p = blockIdx.y, head = p & 7;
    const bool is_q = p < 8;
    const int n0 = blockIdx.x * MSEQ;

    const float* Wih = (is_q ? qWih : kWih) + head * 512;
    const float* Whh = (is_q ? qWhh : kWhh) + (size_t)head * 512 * 128;
    const float* bih = (is_q ? qbih : kbih) + head * 512;
    const float* bhh = (is_q ? qbhh : kbhh) + head * 512;

    // stage permuted recurrent weights as e4m3
    for (int i = tid; i < 512 * 64; i += 512) {
        int row = i >> 6, kp = i & 63;
        int g = row >> 7, j = row & 127;
        int pcol = (j >> 4) * 64 + (g * 2 + ((j >> 3) & 1)) * 8 + (j & 7);
        float w0 = Whh[row * 128 + 2 * kp];
        float w1 = Whh[row * 128 + 2 * kp + 1];
        *(unsigned short*)(ws + pcol * WB + 2 * kp) = f32x2_to_e4m3x2(w0, w1);
    }
    // zero h buffer 0 (e4m3 zero = 0x00)
    for (int i = tid; i < 64 * WB / 4; i += 512) ((unsigned*)hbuf[0])[i] = 0u;
    // prime x for t=0
    if (tid < 64) {
        int n = n0 + tid;
        xs[(tid >> 5) * 64 + (tid & 31)] = (n < NSEQ) ? g_xT[n] : 0.f;
    }

    // per-thread input weights / biases (per gate-tile j = gate*2+uh,
    // covering its column pair = units 16wv + uh*8 + 2r4, +1)
    float2 wf[8], bf[8];
#pragma unroll
    for (int j = 0; j < 8; j++) {
        int g = j >> 1, uh = j & 1;
        int u = 16 * wv + uh * 8 + 2 * r4;
        int r0 = g * 128 + u;
        wf[j] = make_float2(Wih[r0], Wih[r0 + 1]);
        bf[j] = make_float2(bih[r0] + bhh[r0], bih[r0 + 1] + bhh[r0 + 1]);
    }

    __half2 c2[2][2][2];
#pragma unroll
    for (int m = 0; m < 2; m++)
#pragma unroll
        for (int uh = 0; uh < 2; uh++)
#pragma unroll
            for (int pr = 0; pr < 2; pr++) c2[m][uh][pr] = __floats2half2_rn(0.f, 0.f);

    // ldmatrix lane address components (byte offsets, fp8: 16B k-halves)
    const int a_row = (grp & 1) * 8 + ro, a_kB = (grp >> 1) * 16;
    const int b_row = (grp >> 1) * 8 + ro, b_kB = (grp & 1) * 16;
    const int wN0 = wv * 64;
    const __half2 H05 = __floats2half2_rn(0.5f, 0.5f);

    __syncthreads();

    for (int t = 0; t < L_DIM; t++) {
        const unsigned char* hc = hbuf[t & 1];
        unsigned char* hn = hbuf[(t + 1) & 1];

        float acc[2][8][4];
#pragma unroll
        for (int m = 0; m < 2; m++)
#pragma unroll
            for (int j = 0; j < 8; j++)
#pragma unroll
                for (int e = 0; e < 4; e++) acc[m][j][e] = 0.f;

        // Z += H @ W^T over K=128 in 4 k32 chunks
#pragma unroll
        for (int kc = 0; kc < 4; kc++) {
            unsigned a[2][4], b[4][4];
#pragma unroll
            for (int m = 0; m < 2; m++)
                ldsm4(a[m][0], a[m][1], a[m][2], a[m][3],
                      hc + (T * 32 + m * 16 + a_row) * WB + kc * 32 + a_kB);
#pragma unroll
            for (int jj = 0; jj < 4; jj++)
                ldsm4(b[jj][0], b[jj][1], b[jj][2], b[jj][3],
                      ws + (wN0 + jj * 16 + b_row) * WB + kc * 32 + b_kB);
#pragma unroll
            for (int m = 0; m < 2; m++)
#pragma unroll
                for (int jj = 0; jj < 4; jj++) {
                    mma_fp8(acc[m][2 * jj],     a[m], b[jj][0], b[jj][1]);
                    mma_fp8(acc[m][2 * jj + 1], a[m], b[jj][2], b[jj][3]);
                }
        }

        // epilogue: z += x*Wih + b, LSTM nonlinearity (f16x2), h -> fp8 SMEM
        const float* xrow = xs + T * 64 + (t & 1) * 32;
#pragma unroll
        for (int m = 0; m < 2; m++)
#pragma unroll
            for (int pr = 0; pr < 2; pr++) {
                const int rl = m * 16 + q4 + pr * 8;  // local row in team
                const float xr = xrow[rl];
                const int e = 2 * pr;
#pragma unroll
                for (int uh = 0; uh < 2; uh++) {
                    float zi0 = fmaf(xr, wf[0 + uh].x, acc[m][0 + uh][e]     + bf[0 + uh].x);
                    float zi1 = fmaf(xr, wf[0 + uh].y, acc[m][0 + uh][e + 1] + bf[0 + uh].y);
                    float zf0 = fmaf(xr, wf[2 + uh].x, acc[m][2 + uh][e]     + bf[2 + uh].x);
                    float zf1 = fmaf(xr, wf[2 + uh].y, acc[m][2 + uh][e + 1] + bf[2 + uh].y);
                    float zg0 = fmaf(xr, wf[4 + uh].x, acc[m][4 + uh][e]     + bf[4 + uh].x);
                    float zg1 = fmaf(xr, wf[4 + uh].y, acc[m][4 + uh][e + 1] + bf[4 + uh].y);
                    float zo0 = fmaf(xr, wf[6 + uh].x, acc[m][6 + uh][e]     + bf[6 + uh].x);
                    float zo1 = fmaf(xr, wf[6 + uh].y, acc[m][6 + uh][e + 1] + bf[6 + uh].y);
                    __half2 zi = __floats2half2_rn(zi0, zi1);
                    __half2 zf = __floats2half2_rn(zf0, zf1);
                    __half2 zg = __floats2half2_rn(zg0, zg1);
                    __half2 zo = __floats2half2_rn(zo0, zo1);
                    __half2 si = __hfma2(tanh2(__hmul2(zi, H05)), H05, H05);
                    __half2 sf = __hfma2(tanh2(__hmul2(zf, H05)), H05, H05);
                    __half2 so = __hfma2(tanh2(__hmul2(zo, H05)), H05, H05);
                    __half2 tg = tanh2(zg);
                    __half2 cc = __hfma2(sf, c2[m][uh][pr], __hmul2(si, tg));
                    c2[m][uh][pr] = cc;
                    __half2 h2 = __hmul2(so, tanh2(cc));
                    const int u0 = 16 * wv + uh * 8 + 2 * r4;
                    *(unsigned short*)(hn + (T * 32 + rl) * WB + u0) = h2_to_e4m3x2(h2);
                    if (t == L_DIM - 1) {
                        float* ob = (is_q ? g_q : g_k) + (size_t)head * NSEQ * DH;
                        int n1 = n0 + T * 32 + rl;
                        if (n1 < NSEQ) {
                            float2 f = __half22float2(h2);
                            ob[(size_t)n1 * DH + u0]     = f.x;
                            ob[(size_t)n1 * DH + u0 + 1] = f.y;
                        }
                    }
                }
            }

        // x prefetch for t+1 (protected by the team barrier below)
        if (wv == 0 && t < L_DIM - 1) {
            int n = n0 + T * 32 + lane;
            xs[T * 64 + ((t + 1) & 1) * 32 + lane] =
                (n < NSEQ) ? g_xT[(t + 1) * NSEQ + n] : 0.f;
        }
        team_bar(T);
    }
}

// ---------------- attention: scores + leaky + mask + softmax + AV + leaky ----------------
__global__ __launch_bounds__(256, 2) void attn_kernel(const float* __restrict__ graph,
                                                      float* __restrict__ out) {
    extern __shared__ char smem_raw[];
    float* qs = (float*)smem_raw;     // [32][129]
    float* sc = qs + 32 * 129;        // [32][336]
    float* kv = sc + 32 * 336;        // [32][193]

    const int tid = threadIdx.x;
    const int h = blockIdx.z, b = blockIdx.y;
    const int s0 = blockIdx.x * 32;
    const int nrows = min(32, S_DIM - s0);
    const int w = tid >> 5, lane = tid & 31;

    for (int i = tid; i < nrows * 128; i += 256) {
        int r = i >> 7, d = i & 127;
        qs[r * 129 + d] = g_q[((size_t)h * NSEQ + (size_t)b * S_DIM + s0 + r) * 128 + d];
    }
    __syncthreads();

    for (int tk = 0; tk < S_DIM; tk += 32) {
        int tw = min(32, S_DIM - tk);
        for (int i = tid; i < tw * 128; i += 256) {
            int r = i >> 7, d = i & 127;
            kv[r * 129 + d] = g_k[((size_t)h * NSEQ + (size_t)b * S_DIM + tk + r) * 128 + d];
        }
        __syncthreads();
        int si = lane;
        int tl0 = w * 4;
        if (si < nrows && tl0 < tw) {
            float a0 = 0, a1 = 0, a2 = 0, a3 = 0;
            const float* qrow = qs + si * 129;
            const float* k0 = kv + tl0 * 129;
#pragma unroll 4
            for (int d = 0; d < 128; d++) {
                float qv = qrow[d];
                a0 = fmaf(qv, k0[d], a0);
                a1 = fmaf(qv, k0[129 + d], a1);
                a2 = fmaf(qv, k0[258 + d], a2);
                a3 = fmaf(qv, k0[387 + d], a3);
            }
            float av[4] = {a0, a1, a2, a3};
#pragma unroll
            for (int j = 0; j < 4; j++) {
                int t = tk + tl0 + j;
                if (t < S_DIM) {
                    float v = av[j] * 0.08838834764831845f;  // 1/sqrt(128)
                    v = (v >= 0.f) ? v : 0.2f * v;           // leaky
                    float gval = graph[(size_t)t * S_DIM + (s0 + si)];
                    if (s0 + si == t) gval += 1.f;
                    if (gval == 0.f) v += NEG_F;             // mask
                    sc[si * 336 + t] = v;
                }
            }
        }
        __syncthreads();
    }

    for (int si = w; si < nrows; si += 8) {
        float* row = sc + si * 336;
        float m = -3.0e38f;
        for (int j = lane; j < S_DIM; j += 32) m = fmaxf(m, row[j]);
#pragma unroll
        for (int o = 16; o; o >>= 1) m = fmaxf(m, __shfl_xor_sync(0xffffffffu, m, o));
        float ssum = 0.f;
        for (int j = lane; j < S_DIM; j += 32) {
            float e = __expf(row[j] - m);
            row[j] = e;
            ssum += e;
        }
#pragma unroll
        for (int o = 16; o; o >>= 1) ssum += __shfl_xor_sync(0xffffffffu, ssum, o);
        float inv = 1.0f / ssum;
        for (int j = lane; j < S_DIM; j += 32) row[j] *= inv;
    }
    __syncthreads();

    float acc[24];
#pragma unroll
    for (int j = 0; j < 24; j++) acc[j] = 0.f;
    const int si2 = tid >> 3;
    const int lq = tid & 7;
    for (int tk = 0; tk < S_DIM; tk += 32) {
        int tw = min(32, S_DIM - tk);
        for (int i = tid; i < tw * 192; i += 256) {
            int r = i / 192, l = i - r * 192;
            kv[r * 193 + l] = g_v[((size_t)h * NSEQ + (size_t)b * S_DIM + tk + r) * 192 + l];
        }
        __syncthreads();
        if (si2 < nrows) {
            for (int t = 0; t < tw; t++) {
                float a = sc[si2 * 336 + tk + t];
                const float* vrow = kv + t * 193 + lq;
#pragma unroll
                for (int j = 0; j < 24; j++) acc[j] = fmaf(a, vrow[8 * j], acc[j]);
            }
        }
        __syncthreads();
    }
    if (si2 < nrows) {
        size_t base = ((size_t)(b * S_DIM + s0 + si2) * 192) * 8 + h;
#pragma unroll
        for (int j = 0; j < 24; j++) {
            float v = acc[j];
            v = (v >= 0.f) ? v : 0.2f * v;  // final leaky
            out[base + (size_t)(lq + 8 * j) * 8] = v;
        }
    }
}

extern "C" void kernel_launch(void* const* d_in, const int* in_sizes, int n_in,
                              void* d_out, int out_size) {
    const float* x     = (const float*)d_in[0];
    const float* graph = (const float*)d_in[1];
    const float* qWih  = (const float*)d_in[2];
    const float* qWhh  = (const float*)d_in[3];
    const float* qbih  = (const float*)d_in[4];
    const float* qbhh  = (const float*)d_in[5];
    const float* kWih  = (const float*)d_in[6];
    const float* kWhh  = (const float*)d_in[7];
    const float* kbih  = (const float*)d_in[8];
    const float* kbhh  = (const float*)d_in[9];
    const float* vWih  = (const float*)d_in[10];
    const float* vWhh  = (const float*)d_in[11];
    const float* vbih  = (const float*)d_in[12];
    const float* vbhh  = (const float*)d_in[13];
    float* out = (float*)d_out;

    cudaFuncSetAttribute(qk_lstm_fp8, cudaFuncAttributeMaxDynamicSharedMemorySize, QK_SMEM);
    cudaFuncSetAttribute(attn_kernel, cudaFuncAttributeMaxDynamicSharedMemorySize, ATTN_SMEM);

    xT_kernel<<<(NSEQ * L_DIM + 255) / 256, 256>>>(x);
    v_lstm_kernel<<<dim3((NSEQ + 255) / 256, NH), 256>>>(vWih, vWhh, vbih, vbhh);
    qk_lstm_fp8<<<dim3(NBLK, 16), 512, QK_SMEM>>>(qWih, qWhh, qbih, qbhh,
                                                  kWih, kWhh, kbih, kbhh);
    attn_kernel<<<dim3((S_DIM + 31) / 32, B_DIM, NH), 256, ATTN_SMEM>>>(graph, out);
}

// round 7
// speedup vs baseline: 1.2254x; 1.2254x over previous
#include <cuda_runtime.h>
#include <cuda_fp16.h>
#include <math.h>

#define B_DIM 32
#define S_DIM 325
#define L_DIM 192
#define NSEQ (B_DIM * S_DIM)   // 10400
#define DH 128
#define NH 8
#define NEG_F (-1000000000.0f)

// ---- qk fp8 MMA kernel geometry ----
#define MSEQ 32                          // sequences per block (exact: 325*32 = 10400)
#define WB 144                           // byte stride for W / h rows (128 + 16 pad)
#define NBLK (NSEQ / MSEQ)               // 325
#define SM_W  (512 * WB)                 // 73728
#define SM_HA SM_W                       // h buffer 0: [32][WB] fp8
#define SM_HB (SM_W + MSEQ * WB)         // h buffer 1
#define SM_XS (SM_W + 2 * MSEQ * WB)     // x ring: [2 buf][32] f32 = 256B
#define QK_SMEM (SM_XS + 256)            // 83200 bytes -> 2 blocks/SM

#define ATTN_SMEM ((32*129 + 32*336 + 32*193) * 4) // 84224 bytes

// ---- scratch (static device arrays; no allocation allowed) ----
__device__ float g_xT[L_DIM * NSEQ];            // x transposed [t][n]
__device__ float g_q[NH * NSEQ * DH];           // [h][n][d]
__device__ float g_k[NH * NSEQ * DH];           // [h][n][d]
__device__ float g_v[NH * NSEQ * L_DIM];        // [h][n][l]

__device__ __forceinline__ float sigf(float x) { return 1.0f / (1.0f + __expf(-x)); }
__device__ __forceinline__ float tanh_fast(float x) { return 2.0f / (1.0f + __expf(-2.0f * x)) - 1.0f; }

__device__ __forceinline__ __half2 tanh2(__half2 x) {
    unsigned y, xi = *(unsigned*)&x;
    asm("tanh.approx.f16x2 %0, %1;" : "=r"(y) : "r"(xi));
    return *(__half2*)&y;
}
__device__ __forceinline__ unsigned short f32x2_to_e4m3x2(float lo, float hi) {
    unsigned short r;
    asm("cvt.rn.satfinite.e4m3x2.f32 %0, %1, %2;" : "=h"(r) : "f"(hi), "f"(lo));
    return r;
}
__device__ __forceinline__ unsigned short h2_to_e4m3x2(__half2 v) {
    unsigned short r;
    unsigned vi = *(unsigned*)&v;
    asm("cvt.rn.satfinite.e4m3x2.f16x2 %0, %1;" : "=h"(r) : "r"(vi));
    return r;
}

__device__ __forceinline__ void ldsm4(unsigned& r0, unsigned& r1, unsigned& r2, unsigned& r3,
                                      const void* p) {
    unsigned a = (unsigned)__cvta_generic_to_shared(p);
    asm volatile("ldmatrix.sync.aligned.m8n8.x4.shared.b16 {%0,%1,%2,%3}, [%4];"
                 : "=r"(r0), "=r"(r1), "=r"(r2), "=r"(r3) : "r"(a));
}
__device__ __forceinline__ void mma_fp8(float* d, const unsigned* a, unsigned b0, unsigned b1) {
    asm volatile("mma.sync.aligned.m16n8k32.row.col.f32.e4m3.e4m3.f32 "
                 "{%0,%1,%2,%3}, {%4,%5,%6,%7}, {%8,%9}, {%0,%1,%2,%3};"
                 : "+f"(d[0]), "+f"(d[1]), "+f"(d[2]), "+f"(d[3])
                 : "r"(a[0]), "r"(a[1]), "r"(a[2]), "r"(a[3]), "r"(b0), "r"(b1));
}

// ---------------- x transpose: [n][t] -> [t][n] ----------------
__global__ void xT_kernel(const float* __restrict__ x) {
    int i = blockIdx.x * 256 + threadIdx.x;
    if (i < NSEQ * L_DIM) {
        int n = i / L_DIM, t = i - n * L_DIM;
        g_xT[t * NSEQ + n] = x[i];
    }
}

// ---------------- v LSTM (hidden size 1) ----------------
__global__ void v_lstm_kernel(const float* __restrict__ Wih, const float* __restrict__ Whh,
                              const float* __restrict__ bih, const float* __restrict__ bhh) {
    int n = blockIdx.x * 256 + threadIdx.x;
    int h = blockIdx.y;
    if (n >= NSEQ) return;
    float wi[4], wh[4], bb[4];
#pragma unroll
    for (int g = 0; g < 4; g++) {
        wi[g] = Wih[h * 4 + g];
        wh[g] = Whh[h * 4 + g];
        bb[g] = bih[h * 4 + g] + bhh[h * 4 + g];
    }
    float hv = 0.f, c = 0.f;
    float4 buf;
    float* vout = g_v + ((size_t)h * NSEQ + n) * L_DIM;
    for (int t = 0; t < L_DIM; t++) {
        float xv = g_xT[t * NSEQ + n];
        float zi = xv * wi[0] + hv * wh[0] + bb[0];
        float zf = xv * wi[1] + hv * wh[1] + bb[1];
        float zg = xv * wi[2] + hv * wh[2] + bb[2];
        float zo = xv * wi[3] + hv * wh[3] + bb[3];
        c = sigf(zf) * c + sigf(zi) * tanh_fast(zg);
        hv = sigf(zo) * tanh_fast(c);
        ((float*)&buf)[t & 3] = hv;
        if ((t & 3) == 3) *(float4*)(vout + (t - 3)) = buf;
    }
}

// ---------------- q/k LSTM on fp8 tensor cores (m16n8k32 e4m3) ----------------
// grid (325, 16). 256 threads = 8 warps. Block handles 32 sequences of one
// problem (q/k head). Warp wv computes z for 32 seqs x 64 permuted gate cols
// (units [16wv,16wv+16) x 4 gates) and writes the fp8 h chunk = K-columns
// [16wv,16wv+16). One __syncthreads per step. 83.5KB smem + <=128 regs ->
// 2 independent blocks per SM give cross-block pipe overlap.
__global__ __launch_bounds__(256, 2) void qk_lstm_fp8(
    const float* __restrict__ qWih, const float* __restrict__ qWhh,
    const float* __restrict__ qbih, const float* __restrict__ qbhh,
    const float* __restrict__ kWih, const float* __restrict__ kWhh,
    const float* __restrict__ kbih, const float* __restrict__ kbhh) {
    extern __shared__ char sm[];
    unsigned char* ws = (unsigned char*)sm;          // permuted Whh e4m3 [512][WB]
    unsigned char* hbufA = (unsigned char*)(sm + SM_HA);
    unsigned char* hbufB = (unsigned char*)(sm + SM_HB);
    float* xs = (float*)(sm + SM_XS);                // [buf][32]

    const int tid = threadIdx.x;
    const int warp = tid >> 5, lane = tid & 31;
    const int wv = warp;
    const int q4 = lane >> 2, r4 = lane & 3;
    const int grp = lane >> 3, ro = lane & 7;
    const int p = blockIdx.y, head = p & 7;
    const bool is_q = p < 8;
    const int n0 = blockIdx.x * MSEQ;

    const float* Wih = (is_q ? qWih : kWih) + head * 512;
    const float* Whh = (is_q ? qWhh : kWhh) + (size_t)head * 512 * 128;
    const float* bih = (is_q ? qbih : kbih) + head * 512;
    const float* bhh = (is_q ? qbhh : kbhh) + head * 512;

    // stage permuted recurrent weights as e4m3
    for (int i = tid; i < 512 * 64; i += 256) {
        int row = i >> 6, kp = i & 63;
        int g = row >> 7, j = row & 127;
        int pcol = (j >> 4) * 64 + (g * 2 + ((j >> 3) & 1)) * 8 + (j & 7);
        float w0 = Whh[row * 128 + 2 * kp];
        float w1 = Whh[row * 128 + 2 * kp + 1];
        *(unsigned short*)(ws + pcol * WB + 2 * kp) = f32x2_to_e4m3x2(w0, w1);
    }
    // zero h buffer 0 (e4m3 zero = 0x00)
    for (int i = tid; i < MSEQ * WB / 4; i += 256) ((unsigned*)hbufA)[i] = 0u;
    // prime x for t=0
    if (tid < 32) xs[tid] = g_xT[n0 + tid];

    // per-thread input weights / biases in half2 (j = gate*2 + uh; covers the
    // thread's column pair = units 16wv + uh*8 + 2r4, +1)
    __half2 wih2[8], b2[8];
#pragma unroll
    for (int j = 0; j < 8; j++) {
        int g = j >> 1, uh = j & 1;
        int u = 16 * wv + uh * 8 + 2 * r4;
        int r0 = g * 128 + u;
        wih2[j] = __floats2half2_rn(Wih[r0], Wih[r0 + 1]);
        b2[j] = __floats2half2_rn(bih[r0] + bhh[r0], bih[r0 + 1] + bhh[r0 + 1]);
    }

    __half2 c2[2][2][2];
#pragma unroll
    for (int m = 0; m < 2; m++)
#pragma unroll
        for (int uh = 0; uh < 2; uh++)
#pragma unroll
            for (int pr = 0; pr < 2; pr++) c2[m][uh][pr] = __floats2half2_rn(0.f, 0.f);

    // ldmatrix lane address components (byte offsets, fp8: 16B k-halves)
    const int a_row = (grp & 1) * 8 + ro, a_kB = (grp >> 1) * 16;
    const int b_row = (grp >> 1) * 8 + ro, b_kB = (grp & 1) * 16;
    const int wN0 = wv * 64;
    const __half2 H05 = __floats2half2_rn(0.5f, 0.5f);

    __syncthreads();

    for (int t = 0; t < L_DIM; t++) {
        const unsigned char* hc = (t & 1) ? hbufB : hbufA;
        unsigned char* hn = (t & 1) ? hbufA : hbufB;

        float acc[2][8][4];
#pragma unroll
        for (int m = 0; m < 2; m++)
#pragma unroll
            for (int j = 0; j < 8; j++)
#pragma unroll
                for (int e = 0; e < 4; e++) acc[m][j][e] = 0.f;

        // Z += H @ W^T over K=128 in 4 k32 chunks
#pragma unroll
        for (int kc = 0; kc < 4; kc++) {
            unsigned a[2][4], b[4][4];
#pragma unroll
            for (int m = 0; m < 2; m++)
                ldsm4(a[m][0], a[m][1], a[m][2], a[m][3],
                      hc + (m * 16 + a_row) * WB + kc * 32 + a_kB);
#pragma unroll
            for (int jj = 0; jj < 4; jj++)
                ldsm4(b[jj][0], b[jj][1], b[jj][2], b[jj][3],
                      ws + (wN0 + jj * 16 + b_row) * WB + kc * 32 + b_kB);
#pragma unroll
            for (int m = 0; m < 2; m++)
#pragma unroll
                for (int jj = 0; jj < 4; jj++) {
                    mma_fp8(acc[m][2 * jj],     a[m], b[jj][0], b[jj][1]);
                    mma_fp8(acc[m][2 * jj + 1], a[m], b[jj][2], b[jj][3]);
                }
        }

        // epilogue: z += x*Wih + b (half2), LSTM nonlinearity, h -> fp8 SMEM
        const float* xrow = xs + (t & 1) * 32;
#pragma unroll
        for (int m = 0; m < 2; m++)
#pragma unroll
            for (int pr = 0; pr < 2; pr++) {
                const int rl = m * 16 + q4 + pr * 8;   // row (seq) in block
                const __half2 xh = __float2half2_rn(xrow[rl]);
                const int e = 2 * pr;
#pragma unroll
                for (int uh = 0; uh < 2; uh++) {
                    __half2 zi = __hfma2(xh, wih2[0 + uh],
                        __hadd2(__floats2half2_rn(acc[m][0 + uh][e], acc[m][0 + uh][e + 1]), b2[0 + uh]));
                    __half2 zf = __hfma2(xh, wih2[2 + uh],
                        __hadd2(__floats2half2_rn(acc[m][2 + uh][e], acc[m][2 + uh][e + 1]), b2[2 + uh]));
                    __half2 zg = __hfma2(xh, wih2[4 + uh],
                        __hadd2(__floats2half2_rn(acc[m][4 + uh][e], acc[m][4 + uh][e + 1]), b2[4 + uh]));
                    __half2 zo = __hfma2(xh, wih2[6 + uh],
                        __hadd2(__floats2half2_rn(acc[m][6 + uh][e], acc[m][6 + uh][e + 1]), b2[6 + uh]));
                    __half2 si = __hfma2(tanh2(__hmul2(zi, H05)), H05, H05);
                    __half2 sf = __hfma2(tanh2(__hmul2(zf, H05)), H05, H05);
                    __half2 so = __hfma2(tanh2(__hmul2(zo, H05)), H05, H05);
                    __half2 tg = tanh2(zg);
                    __half2 cc = __hfma2(sf, c2[m][uh][pr], __hmul2(si, tg));
                    c2[m][uh][pr] = cc;
                    __half2 h2 = __hmul2(so, tanh2(cc));
                    const int u0 = 16 * wv + uh * 8 + 2 * r4;
                    *(unsigned short*)(hn + rl * WB + u0) = h2_to_e4m3x2(h2);
                    if (t == L_DIM - 1) {
                        float* ob = (is_q ? g_q : g_k) + (size_t)head * NSEQ * DH;
                        float2 f = __half22float2(h2);
                        ob[(size_t)(n0 + rl) * DH + u0]     = f.x;
                        ob[(size_t)(n0 + rl) * DH + u0 + 1] = f.y;
                    }
                }
            }

        // x prefetch for t+1 (protected by the barrier below)
        if (warp == 0 && t < L_DIM - 1)
            xs[((t + 1) & 1) * 32 + lane] = g_xT[(t + 1) * NSEQ + n0 + lane];
        __syncthreads();
    }
}

// ---------------- attention: scores + leaky + mask + softmax + AV + leaky ----------------
__global__ __launch_bounds__(256, 2) void attn_kernel(const float* __restrict__ graph,
                                                      float* __restrict__ out) {
    extern __shared__ char smem_raw[];
    float* qs = (float*)smem_raw;     // [32][129]
    float* sc = qs + 32 * 129;        // [32][336]
    float* kv = sc + 32 * 336;        // [32][193]

    const int tid = threadIdx.x;
    const int h = blockIdx.z, b = blockIdx.y;
    const int s0 = blockIdx.x * 32;
    const int nrows = min(32, S_DIM - s0);
    const int w = tid >> 5, lane = tid & 31;

    for (int i = tid; i < nrows * 128; i += 256) {
        int r = i >> 7, d = i & 127;
        qs[r * 129 + d] = g_q[((size_t)h * NSEQ + (size_t)b * S_DIM + s0 + r) * 128 + d];
    }
    __syncthreads();

    for (int tk = 0; tk < S_DIM; tk += 32) {
        int tw = min(32, S_DIM - tk);
        for (int i = tid; i < tw * 128; i += 256) {
            int r = i >> 7, d = i & 127;
            kv[r * 129 + d] = g_k[((size_t)h * NSEQ + (size_t)b * S_DIM + tk + r) * 128 + d];
        }
        __syncthreads();
        int si = lane;
        int tl0 = w * 4;
        if (si < nrows && tl0 < tw) {
            float a0 = 0, a1 = 0, a2 = 0, a3 = 0;
            const float* qrow = qs + si * 129;
            const float* k0 = kv + tl0 * 129;
#pragma unroll 4
            for (int d = 0; d < 128; d++) {
                float qv = qrow[d];
                a0 = fmaf(qv, k0[d], a0);
                a1 = fmaf(qv, k0[129 + d], a1);
                a2 = fmaf(qv, k0[258 + d], a2);
                a3 = fmaf(qv, k0[387 + d], a3);
            }
            float av[4] = {a0, a1, a2, a3};
#pragma unroll
            for (int j = 0; j < 4; j++) {
                int t = tk + tl0 + j;
                if (t < S_DIM) {
                    float v = av[j] * 0.08838834764831845f;  // 1/sqrt(128)
                    v = (v >= 0.f) ? v : 0.2f * v;           // leaky
                    float gval = graph[(size_t)t * S_DIM + (s0 + si)];
                    if (s0 + si == t) gval += 1.f;
                    if (gval == 0.f) v += NEG_F;             // mask
                    sc[si * 336 + t] = v;
                }
            }
        }
        __syncthreads();
    }

    for (int si = w; si < nrows; si += 8) {
        float* row = sc + si * 336;
        float m = -3.0e38f;
        for (int j = lane; j < S_DIM; j += 32) m = fmaxf(m, row[j]);
#pragma unroll
        for (int o = 16; o; o >>= 1) m = fmaxf(m, __shfl_xor_sync(0xffffffffu, m, o));
        float ssum = 0.f;
        for (int j = lane; j < S_DIM; j += 32) {
            float e = __expf(row[j] - m);
            row[j] = e;
            ssum += e;
        }
#pragma unroll
        for (int o = 16; o; o >>= 1) ssum += __shfl_xor_sync(0xffffffffu, ssum, o);
        float inv = 1.0f / ssum;
        for (int j = lane; j < S_DIM; j += 32) row[j] *= inv;
    }
    __syncthreads();

    float acc[24];
#pragma unroll
    for (int j = 0; j < 24; j++) acc[j] = 0.f;
    const int si2 = tid >> 3;
    const int lq = tid & 7;
    for (int tk = 0; tk < S_DIM; tk += 32) {
        int tw = min(32, S_DIM - tk);
        for (int i = tid; i < tw * 192; i += 256) {
            int r = i / 192, l = i - r * 192;
            kv[r * 193 + l] = g_v[((size_t)h * NSEQ + (size_t)b * S_DIM + tk + r) * 192 + l];
        }
        __syncthreads();
        if (si2 < nrows) {
            for (int t = 0; t < tw; t++) {
                float a = sc[si2 * 336 + tk + t];
                const float* vrow = kv + t * 193 + lq;
#pragma unroll
                for (int j = 0; j < 24; j++) acc[j] = fmaf(a, vrow[8 * j], acc[j]);
            }
        }
        __syncthreads();
    }
    if (si2 < nrows) {
        size_t base = ((size_t)(b * S_DIM + s0 + si2) * 192) * 8 + h;
#pragma unroll
        for (int j = 0; j < 24; j++) {
            float v = acc[j];
            v = (v >= 0.f) ? v : 0.2f * v;  // final leaky
            out[base + (size_t)(lq + 8 * j) * 8] = v;
        }
    }
}

extern "C" void kernel_launch(void* const* d_in, const int* in_sizes, int n_in,
                              void* d_out, int out_size) {
    const float* x     = (const float*)d_in[0];
    const float* graph = (const float*)d_in[1];
    const float* qWih  = (const float*)d_in[2];
    const float* qWhh  = (const float*)d_in[3];
    const float* qbih  = (const float*)d_in[4];
    const float* qbhh  = (const float*)d_in[5];
    const float* kWih  = (const float*)d_in[6];
    const float* kWhh  = (const float*)d_in[7];
    const float* kbih  = (const float*)d_in[8];
    const float* kbhh  = (const float*)d_in[9];
    const float* vWih  = (const float*)d_in[10];
    const float* vWhh  = (const float*)d_in[11];
    const float* vbih  = (const float*)d_in[12];
    const float* vbhh  = (const float*)d_in[13];
    float* out = (float*)d_out;

    cudaFuncSetAttribute(qk_lstm_fp8, cudaFuncAttributeMaxDynamicSharedMemorySize, QK_SMEM);
    cudaFuncSetAttribute(attn_kernel, cudaFuncAttributeMaxDynamicSharedMemorySize, ATTN_SMEM);

    xT_kernel<<<(NSEQ * L_DIM + 255) / 256, 256>>>(x);
    v_lstm_kernel<<<dim3((NSEQ + 255) / 256, NH), 256>>>(vWih, vWhh, vbih, vbhh);
    qk_lstm_fp8<<<dim3(NBLK, 16), 256, QK_SMEM>>>(qWih, qWhh, qbih, qbhh,
                                                  kWih, kWhh, kbih, kbhh);
    attn_kernel<<<dim3((S_DIM + 31) / 32, B_DIM, NH), 256, ATTN_SMEM>>>(graph, out);
}

// round 8
// speedup vs baseline: 1.2256x; 1.0002x over previous
#include <cuda_runtime.h>
#include <cuda_fp16.h>
#include <math.h>

#define B_DIM 32
#define S_DIM 325
#define L_DIM 192
#define NSEQ (B_DIM * S_DIM)   // 10400
#define DH 128
#define NH 8
#define NEG_F (-1000000000.0f)

// ---- qk fp8 MMA kernel geometry ----
#define MSEQ 32                          // sequences per block (exact: 325*32 = 10400)
#define WB 144                           // byte stride for W / h rows (128 + 16 pad)
#define NBLK (NSEQ / MSEQ)               // 325
#define SM_W  (512 * WB)                 // 73728
#define SM_HA SM_W                       // h buffer 0: [32][WB] fp8
#define SM_HB (SM_W + MSEQ * WB)         // h buffer 1
#define SM_XS (SM_W + 2 * MSEQ * WB)     // x ring: [2 buf][32] f32 = 256B
#define QK_SMEM (SM_XS + 256)            // 83200 bytes -> 2 blocks/SM

#define ATTN_SMEM ((32*129 + 32*336 + 32*193) * 4) // 84224 bytes

// ---- scratch (static device arrays; no allocation allowed) ----
__device__ float g_xT[L_DIM * NSEQ];            // x transposed [t][n]
__device__ float g_q[NH * NSEQ * DH];           // [h][n][d]
__device__ float g_k[NH * NSEQ * DH];           // [h][n][d]
__device__ float g_v[NH * NSEQ * L_DIM];        // [h][n][l]

__device__ __forceinline__ float sigf(float x) { return 1.0f / (1.0f + __expf(-x)); }
__device__ __forceinline__ float tanh_fast(float x) { return 2.0f / (1.0f + __expf(-2.0f * x)) - 1.0f; }

__device__ __forceinline__ __half2 tanh2(__half2 x) {
    unsigned y, xi = *(unsigned*)&x;
    asm("tanh.approx.f16x2 %0, %1;" : "=r"(y) : "r"(xi));
    return *(__half2*)&y;
}
__device__ __forceinline__ unsigned short f32x2_to_e4m3x2(float lo, float hi) {
    unsigned short r;
    asm("cvt.rn.satfinite.e4m3x2.f32 %0, %1, %2;" : "=h"(r) : "f"(hi), "f"(lo));
    return r;
}
__device__ __forceinline__ unsigned short h2_to_e4m3x2(__half2 v) {
    unsigned short r;
    unsigned vi = *(unsigned*)&v;
    asm("cvt.rn.satfinite.e4m3x2.f16x2 %0, %1;" : "=h"(r) : "r"(vi));
    return r;
}

__device__ __forceinline__ void ldsm4(unsigned& r0, unsigned& r1, unsigned& r2, unsigned& r3,
                                      const void* p) {
    unsigned a = (unsigned)__cvta_generic_to_shared(p);
    asm volatile("ldmatrix.sync.aligned.m8n8.x4.shared.b16 {%0,%1,%2,%3}, [%4];"
                 : "=r"(r0), "=r"(r1), "=r"(r2), "=r"(r3) : "r"(a));
}
__device__ __forceinline__ void mma_fp8(float* d, const unsigned* a, unsigned b0, unsigned b1) {
    asm volatile("mma.sync.aligned.m16n8k32.row.col.f32.e4m3.e4m3.f32 "
                 "{%0,%1,%2,%3}, {%4,%5,%6,%7}, {%8,%9}, {%0,%1,%2,%3};"
                 : "+f"(d[0]), "+f"(d[1]), "+f"(d[2]), "+f"(d[3])
                 : "r"(a[0]), "r"(a[1]), "r"(a[2]), "r"(a[3]), "r"(b0), "r"(b1));
}

// ---------------- x transpose: [n][t] -> [t][n] ----------------
__global__ void xT_kernel(const float* __restrict__ x) {
    int i = blockIdx.x * 256 + threadIdx.x;
    if (i < NSEQ * L_DIM) {
        int n = i / L_DIM, t = i - n * L_DIM;
        g_xT[t * NSEQ + n] = x[i];
    }
}

// ---------------- v LSTM (hidden size 1) ----------------
__global__ void v_lstm_kernel(const float* __restrict__ Wih, const float* __restrict__ Whh,
                              const float* __restrict__ bih, const float* __restrict__ bhh) {
    int n = blockIdx.x * 256 + threadIdx.x;
    int h = blockIdx.y;
    if (n >= NSEQ) return;
    float wi[4], wh[4], bb[4];
#pragma unroll
    for (int g = 0; g < 4; g++) {
        wi[g] = Wih[h * 4 + g];
        wh[g] = Whh[h * 4 + g];
        bb[g] = bih[h * 4 + g] + bhh[h * 4 + g];
    }
    float hv = 0.f, c = 0.f;
    float4 buf;
    float* vout = g_v + ((size_t)h * NSEQ + n) * L_DIM;
    for (int t = 0; t < L_DIM; t++) {
        float xv = g_xT[t * NSEQ + n];
        float zi = xv * wi[0] + hv * wh[0] + bb[0];
        float zf = xv * wi[1] + hv * wh[1] + bb[1];
        float zg = xv * wi[2] + hv * wh[2] + bb[2];
        float zo = xv * wi[3] + hv * wh[3] + bb[3];
        c = sigf(zf) * c + sigf(zi) * tanh_fast(zg);
        hv = sigf(zo) * tanh_fast(c);
        ((float*)&buf)[t & 3] = hv;
        if ((t & 3) == 3) *(float4*)(vout + (t - 3)) = buf;
    }
}

// ---------------- q/k LSTM on fp8 tensor cores (m16n8k32 e4m3) ----------------
// grid (325, 16). 256 threads = 8 warps. Block handles 32 sequences of one
// problem (q/k head). Warp wv computes z for 32 seqs x 64 permuted gate cols
// (units [16wv,16wv+16) x 4 gates) and writes the fp8 h chunk = K-columns
// [16wv,16wv+16). One __syncthreads per step. 83.5KB smem + <=128 regs ->
// 2 independent blocks per SM give cross-block pipe overlap.
__global__ __launch_bounds__(256, 2) void qk_lstm_fp8(
    const float* __restrict__ qWih, const float* __restrict__ qWhh,
    const float* __restrict__ qbih, const float* __restrict__ qbhh,
    const float* __restrict__ kWih, const float* __restrict__ kWhh,
    const float* __restrict__ kbih, const float* __restrict__ kbhh) {
    extern __shared__ char sm[];
    unsigned char* ws = (unsigned char*)sm;          // permuted Whh e4m3 [512][WB]
    unsigned char* hbufA = (unsigned char*)(sm + SM_HA);
    unsigned char* hbufB = (unsigned char*)(sm + SM_HB);
    float* xs = (float*)(sm + SM_XS);                // [buf][32]

    const int tid = threadIdx.x;
    const int warp = tid >> 5, lane = tid & 31;
    const int wv = warp;
    const int q4 = lane >> 2, r4 = lane & 3;
    const int grp = lane >> 3, ro = lane & 7;
    const int p = blockIdx.y, head = p & 7;
    const bool is_q = p < 8;
    const int n0 = blockIdx.x * MSEQ;

    const float* Wih = (is_q ? qWih : kWih) + head * 512;
    const float* Whh = (is_q ? qWhh : kWhh) + (size_t)head * 512 * 128;
    const float* bih = (is_q ? qbih : kbih) + head * 512;
    const float* bhh = (is_q ? qbhh : kbhh) + head * 512;

    // stage permuted recurrent weights as e4m3
    for (int i = tid; i < 512 * 64; i += 256) {
        int row = i >> 6, kp = i & 63;
        int g = row >> 7, j = row & 127;
        int pcol = (j >> 4) * 64 + (g * 2 + ((j >> 3) & 1)) * 8 + (j & 7);
        float w0 = Whh[row * 128 + 2 * kp];
        float w1 = Whh[row * 128 + 2 * kp + 1];
        *(unsigned short*)(ws + pcol * WB + 2 * kp) = f32x2_to_e4m3x2(w0, w1);
    }
    // zero h buffer 0 (e4m3 zero = 0x00)
    for (int i = tid; i < MSEQ * WB / 4; i += 256) ((unsigned*)hbufA)[i] = 0u;
    // prime x for t=0
    if (tid < 32) xs[tid] = g_xT[n0 + tid];

    // per-thread input weights / biases in half2 (j = gate*2 + uh; covers the
    // thread's column pair = units 16wv + uh*8 + 2r4, +1)
    __half2 wih2[8], b2[8];
#pragma unroll
    for (int j = 0; j < 8; j++) {
        int g = j >> 1, uh = j & 1;
        int u = 16 * wv + uh * 8 + 2 * r4;
        int r0 = g * 128 + u;
        wih2[j] = __floats2half2_rn(Wih[r0], Wih[r0 + 1]);
        b2[j] = __floats2half2_rn(bih[r0] + bhh[r0], bih[r0 + 1] + bhh[r0 + 1]);
    }

    __half2 c2[2][2][2];
#pragma unroll
    for (int m = 0; m < 2; m++)
#pragma unroll
        for (int uh = 0; uh < 2; uh++)
#pragma unroll
            for (int pr = 0; pr < 2; pr++) c2[m][uh][pr] = __floats2half2_rn(0.f, 0.f);

    // ldmatrix lane address components (byte offsets, fp8: 16B k-halves)
    const int a_row = (grp & 1) * 8 + ro, a_kB = (grp >> 1) * 16;
    const int b_row = (grp >> 1) * 8 + ro, b_kB = (grp & 1) * 16;
    const int wN0 = wv * 64;
    const __half2 H05 = __floats2half2_rn(0.5f, 0.5f);

    __syncthreads();

    for (int t = 0; t < L_DIM; t++) {
        const unsigned char* hc = (t & 1) ? hbufB : hbufA;
        unsigned char* hn = (t & 1) ? hbufA : hbufB;

        float acc[2][8][4];
#pragma unroll
        for (int m = 0; m < 2; m++)
#pragma unroll
            for (int j = 0; j < 8; j++)
#pragma unroll
                for (int e = 0; e < 4; e++) acc[m][j][e] = 0.f;

        // Z += H @ W^T over K=128 in 4 k32 chunks
#pragma unroll
        for (int kc = 0; kc < 4; kc++) {
            unsigned a[2][4], b[4][4];
#pragma unroll
            for (int m = 0; m < 2; m++)
                ldsm4(a[m][0], a[m][1], a[m][2], a[m][3],
                      hc + (m * 16 + a_row) * WB + kc * 32 + a_kB);
#pragma unroll
            for (int jj = 0; jj < 4; jj++)
                ldsm4(b[jj][0], b[jj][1], b[jj][2], b[jj][3],
                      ws + (wN0 + jj * 16 + b_row) * WB + kc * 32 + b_kB);
#pragma unroll
            for (int m = 0; m < 2; m++)
#pragma unroll
                for (int jj = 0; jj < 4; jj++) {
                    mma_fp8(acc[m][2 * jj],     a[m], b[jj][0], b[jj][1]);
                    mma_fp8(acc[m][2 * jj + 1], a[m], b[jj][2], b[jj][3]);
                }
        }

        // epilogue: z += x*Wih + b (half2), LSTM nonlinearity, h -> fp8 SMEM
        const float* xrow = xs + (t & 1) * 32;
#pragma unroll
        for (int m = 0; m < 2; m++)
#pragma unroll
            for (int pr = 0; pr < 2; pr++) {
                const int rl = m * 16 + q4 + pr * 8;   // row (seq) in block
                const __half2 xh = __float2half2_rn(xrow[rl]);
                const int e = 2 * pr;
#pragma unroll
                for (int uh = 0; uh < 2; uh++) {
                    __half2 zi = __hfma2(xh, wih2[0 + uh],
                        __hadd2(__floats2half2_rn(acc[m][0 + uh][e], acc[m][0 + uh][e + 1]), b2[0 + uh]));
                    __half2 zf = __hfma2(xh, wih2[2 + uh],
                        __hadd2(__floats2half2_rn(acc[m][2 + uh][e], acc[m][2 + uh][e + 1]), b2[2 + uh]));
                    __half2 zg = __hfma2(xh, wih2[4 + uh],
                        __hadd2(__floats2half2_rn(acc[m][4 + uh][e], acc[m][4 + uh][e + 1]), b2[4 + uh]));
                    __half2 zo = __hfma2(xh, wih2[6 + uh],
                        __hadd2(__floats2half2_rn(acc[m][6 + uh][e], acc[m][6 + uh][e + 1]), b2[6 + uh]));
                    __half2 si = __hfma2(tanh2(__hmul2(zi, H05)), H05, H05);
                    __half2 sf = __hfma2(tanh2(__hmul2(zf, H05)), H05, H05);
                    __half2 so = __hfma2(tanh2(__hmul2(zo, H05)), H05, H05);
                    __half2 tg = tanh2(zg);
                    __half2 cc = __hfma2(sf, c2[m][uh][pr], __hmul2(si, tg));
                    c2[m][uh][pr] = cc;
                    __half2 h2 = __hmul2(so, tanh2(cc));
                    const int u0 = 16 * wv + uh * 8 + 2 * r4;
                    *(unsigned short*)(hn + rl * WB + u0) = h2_to_e4m3x2(h2);
                    if (t == L_DIM - 1) {
                        float* ob = (is_q ? g_q : g_k) + (size_t)head * NSEQ * DH;
                        float2 f = __half22float2(h2);
                        ob[(size_t)(n0 + rl) * DH + u0]     = f.x;
                        ob[(size_t)(n0 + rl) * DH + u0 + 1] = f.y;
                    }
                }
            }

        // x prefetch for t+1 (protected by the barrier below)
        if (warp == 0 && t < L_DIM - 1)
            xs[((t + 1) & 1) * 32 + lane] = g_xT[(t + 1) * NSEQ + n0 + lane];
        __syncthreads();
    }
}

// ---------------- attention: scores + leaky + mask + softmax + AV + leaky ----------------
__global__ __launch_bounds__(256, 2) void attn_kernel(const float* __restrict__ graph,
                                                      float* __restrict__ out) {
    extern __shared__ char smem_raw[];
    float* qs = (float*)smem_raw;     // [32][129]
    float* sc = qs + 32 * 129;        // [32][336]
    float* kv = sc + 32 * 336;        // [32][193]

    const int tid = threadIdx.x;
    const int h = blockIdx.z, b = blockIdx.y;
    const int s0 = blockIdx.x * 32;
    const int nrows = min(32, S_DIM - s0);
    const int w = tid >> 5, lane = tid & 31;

    for (int i = tid; i < nrows * 128; i += 256) {
        int r = i >> 7, d = i & 127;
        qs[r * 129 + d] = g_q[((size_t)h * NSEQ + (size_t)b * S_DIM + s0 + r) * 128 + d];
    }
    __syncthreads();

    for (int tk = 0; tk < S_DIM; tk += 32) {
        int tw = min(32, S_DIM - tk);
        for (int i = tid; i < tw * 128; i += 256) {
            int r = i >> 7, d = i & 127;
            kv[r * 129 + d] = g_k[((size_t)h * NSEQ + (size_t)b * S_DIM + tk + r) * 128 + d];
        }
        __syncthreads();
        int si = lane;
        int tl0 = w * 4;
        if (si < nrows && tl0 < tw) {
            float a0 = 0, a1 = 0, a2 = 0, a3 = 0;
            const float* qrow = qs + si * 129;
            const float* k0 = kv + tl0 * 129;
#pragma unroll 4
            for (int d = 0; d < 128; d++) {
                float qv = qrow[d];
                a0 = fmaf(qv, k0[d], a0);
                a1 = fmaf(qv, k0[129 + d], a1);
                a2 = fmaf(qv, k0[258 + d], a2);
                a3 = fmaf(qv, k0[387 + d], a3);
            }
            float av[4] = {a0, a1, a2, a3};
#pragma unroll
            for (int j = 0; j < 4; j++) {
                int t = tk + tl0 + j;
                if (t < S_DIM) {
                    float v = av[j] * 0.08838834764831845f;  // 1/sqrt(128)
                    v = (v >= 0.f) ? v : 0.2f * v;           // leaky
                    float gval = graph[(size_t)t * S_DIM + (s0 + si)];
                    if (s0 + si == t) gval += 1.f;
                    if (gval == 0.f) v += NEG_F;             // mask
                    sc[si * 336 + t] = v;
                }
            }
        }
        __syncthreads();
    }

    for (int si = w; si < nrows; si += 8) {
        float* row = sc + si * 336;
        float m = -3.0e38f;
        for (int j = lane; j < S_DIM; j += 32) m = fmaxf(m, row[j]);
#pragma unroll
        for (int o = 16; o; o >>= 1) m = fmaxf(m, __shfl_xor_sync(0xffffffffu, m, o));
        float ssum = 0.f;
        for (int j = lane; j < S_DIM; j += 32) {
            float e = __expf(row[j] - m);
            row[j] = e;
            ssum += e;
        }
#pragma unroll
        for (int o = 16; o; o >>= 1) ssum += __shfl_xor_sync(0xffffffffu, ssum, o);
        float inv = 1.0f / ssum;
        for (int j = lane; j < S_DIM; j += 32) row[j] *= inv;
    }
    __syncthreads();

    float acc[24];
#pragma unroll
    for (int j = 0; j < 24; j++) acc[j] = 0.f;
    const int si2 = tid >> 3;
    const int lq = tid & 7;
    for (int tk = 0; tk < S_DIM; tk += 32) {
        int tw = min(32, S_DIM - tk);
        for (int i = tid; i < tw * 192; i += 256) {
            int r = i / 192, l = i - r * 192;
            kv[r * 193 + l] = g_v[((size_t)h * NSEQ + (size_t)b * S_DIM + tk + r) * 192 + l];
        }
        __syncthreads();
        if (si2 < nrows) {
            for (int t = 0; t < tw; t++) {
                float a = sc[si2 * 336 + tk + t];
                const float* vrow = kv + t * 193 + lq;
#pragma unroll
                for (int j = 0; j < 24; j++) acc[j] = fmaf(a, vrow[8 * j], acc[j]);
            }
        }
        __syncthreads();
    }
    if (si2 < nrows) {
        size_t base = ((size_t)(b * S_DIM + s0 + si2) * 192) * 8 + h;
#pragma unroll
        for (int j = 0; j < 24; j++) {
            float v = acc[j];
            v = (v >= 0.f) ? v : 0.2f * v;  // final leaky
            out[base + (size_t)(lq + 8 * j) * 8] = v;
        }
    }
}

extern "C" void kernel_launch(void* const* d_in, const int* in_sizes, int n_in,
                              void* d_out, int out_size) {
    const float* x     = (const float*)d_in[0];
    const float* graph = (const float*)d_in[1];
    const float* qWih  = (const float*)d_in[2];
    const float* qWhh  = (const float*)d_in[3];
    const float* qbih  = (const float*)d_in[4];
    const float* qbhh  = (const float*)d_in[5];
    const float* kWih  = (const float*)d_in[6];
    const float* kWhh  = (const float*)d_in[7];
    const float* kbih  = (const float*)d_in[8];
    const float* kbhh  = (const float*)d_in[9];
    const float* vWih  = (const float*)d_in[10];
    const float* vWhh  = (const float*)d_in[11];
    const float* vbih  = (const float*)d_in[12];
    const float* vbhh  = (const float*)d_in[13];
    float* out = (float*)d_out;

    cudaFuncSetAttribute(qk_lstm_fp8, cudaFuncAttributeMaxDynamicSharedMemorySize, QK_SMEM);
    cudaFuncSetAttribute(attn_kernel, cudaFuncAttributeMaxDynamicSharedMemorySize, ATTN_SMEM);

    xT_kernel<<<(NSEQ * L_DIM + 255) / 256, 256>>>(x);
    v_lstm_kernel<<<dim3((NSEQ + 255) / 256, NH), 256>>>(vWih, vWhh, vbih, vbhh);
    qk_lstm_fp8<<<dim3(NBLK, 16), 256, QK_SMEM>>>(qWih, qWhh, qbih, qbhh,
                                                  kWih, kWhh, kbih, kbhh);
    attn_kernel<<<dim3((S_DIM + 31) / 32, B_DIM, NH), 256, ATTN_SMEM>>>(graph, out);
}